// round 16
// baseline (speedup 1.0000x reference)
#include <cuda_runtime.h>
#include <math.h>
#include <stdint.h>

#define BB   8
#define C1   512
#define C2   256
#define SD   512
#define H0   64
#define H1   128
#define NPIX   (H1*H1)      // 16384
#define NPIX0  (H0*H0)      // 4096
#define NT4  8192           // 4x4 output tiles: 8 b * 32 * 32

typedef unsigned long long ull;

__device__ __forceinline__ void ffma2(ull& acc, ull a, ull b) {
    asm("fma.rn.f32x2 %0, %1, %2, %0;" : "+l"(acc) : "l"(a), "l"(b));
}
__device__ __forceinline__ void unpack2(ull p, float& lo, float& hi) {
    unsigned int a, b;
    asm("mov.b64 {%0, %1}, %2;" : "=r"(a), "=r"(b) : "l"(p));
    lo = __uint_as_float(a); hi = __uint_as_float(b);
}
__device__ __forceinline__ uint32_t smem_u32(const void* p) {
    uint32_t a;
    asm("{ .reg .u64 t; cvta.to.shared.u64 t, %1; cvt.u32.u64 %0, t; }" : "=r"(a) : "l"(p));
    return a;
}
__device__ __forceinline__ void cp16(uint32_t dst, const float* src) {
    asm volatile("cp.async.ca.shared.global [%0], [%1], 16;" :: "r"(dst), "l"(src));
}
#define CP_COMMIT() asm volatile("cp.async.commit_group;")

// ---------------- scratch (device globals; no allocation) ----------------
__device__ float g_s1[BB*C1];
__device__ float g_s2[BB*C2];
__device__ float g_s3[BB*C2];
__device__ float g_e1[BB*C2];
__device__ float g_e2[BB*C2];
__device__ float g_wsq1[C2*C1];
__device__ float g_wsq2[C2*C2];
__device__ float g_up [(size_t)BB*C1*NPIX];        // 268 MB upsampled*s1 input
__device__ float g_h1 [(size_t)BB*C2*NPIX];        // 134 MB conv1 out * s2
__device__ float g_U1 [(size_t)36*C1*2*C2];        // 37.7 MB winograd weights [t][ci][2o] (dup pairs)
__device__ float g_U2 [(size_t)36*C2*2*C2];        // 18.9 MB
__device__ float g_V  [(size_t)36*C1*NT4];         // 604 MB transformed input [t][ci][tile]
__device__ float g_M  [(size_t)36*C2*NT4];         // 302 MB GEMM out [t][o][tile]

// ---------------- styles ----------------
__global__ void k_styles(const float* __restrict__ w1, const float* __restrict__ w2,
                         const float* __restrict__ m1w, const float* __restrict__ m1b,
                         const float* __restrict__ m2w, const float* __restrict__ m2b,
                         const float* __restrict__ m3w, const float* __restrict__ m3b)
{
    int t = blockIdx.x*blockDim.x + threadIdx.x;
    const float inv = rsqrtf((float)SD);
    if (t < BB*C1) {
        int b = t / C1, i = t % C1;
        float a = 0.f;
        for (int k = 0; k < SD; k++) a += w1[b*SD+k] * m1w[i*SD+k];
        g_s1[t] = a*inv + m1b[i];
    } else if (t < BB*C1 + BB*C2) {
        int u = t - BB*C1; int b = u / C2, i = u % C2;
        float a = 0.f;
        for (int k = 0; k < SD; k++) a += w2[b*SD+k] * m2w[i*SD+k];
        g_s2[u] = a*inv + m2b[i];
    } else if (t < BB*C1 + 2*BB*C2) {
        int u = t - BB*C1 - BB*C2; int b = u / C2, i = u % C2;
        float a = 0.f;
        for (int k = 0; k < SD; k++) a += w2[b*SD+k] * m3w[i*SD+k];
        g_s3[u] = a*inv + m3b[i];
    }
}

// ---------------- per-(o,i) sum of squared taps ----------------
__global__ void k_wsq(const float* __restrict__ w1c, const float* __restrict__ w2c)
{
    int t = blockIdx.x*blockDim.x + threadIdx.x;
    if (t < C2*C1) {
        float a = 0.f;
        #pragma unroll
        for (int k = 0; k < 9; k++) { float v = w1c[t*9+k]; a += v*v; }
        g_wsq1[t] = a;
    } else if (t < C2*C1 + C2*C2) {
        int u = t - C2*C1;
        float a = 0.f;
        #pragma unroll
        for (int k = 0; k < 9; k++) { float v = w2c[u*9+k]; a += v*v; }
        g_wsq2[u] = a;
    }
}

// ---------------- demod scalars ----------------
__global__ void k_demod()
{
    int t = blockIdx.x*blockDim.x + threadIdx.x;
    const float sc1 = rsqrtf((float)(C1*9));
    const float sc2 = rsqrtf((float)(C2*9));
    if (t < BB*C2) {
        int b = t / C2, o = t % C2;
        float a = 0.f;
        for (int i = 0; i < C1; i++) { float s = g_s1[b*C1+i]; a += g_wsq1[o*C1+i]*s*s; }
        g_e1[t] = sc1 * rsqrtf(sc1*sc1*a + 1e-8f);
    } else if (t < 2*BB*C2) {
        int u = t - BB*C2; int b = u / C2, o = u % C2;
        float a = 0.f;
        for (int i = 0; i < C2; i++) { float s = g_s2[b*C2+i]; a += g_wsq2[o*C2+i]*s*s; }
        g_e2[u] = sc2 * rsqrtf(sc2*sc2*a + 1e-8f);
    }
}

// ---------------- F(4,3) weight transform, DUPLICATED pairs: U[t][ci][2o]={u,u} ----------------
__global__ void k_wt4(const float* __restrict__ w, float* __restrict__ U, int CIN)
{
    int idx = blockIdx.x*256 + threadIdx.x;
    if (idx >= CIN*C2) return;
    int o = idx & 255, ci = idx >> 8;
    const float* g = w + ((size_t)o*CIN + ci)*9;   // g[ky*3+kx]
    float a[6][3];
    #pragma unroll
    for (int c = 0; c < 3; c++) {
        float g0 = g[c], g1 = g[3+c], g2 = g[6+c];
        a[0][c] = 0.25f*g0;
        a[1][c] = -(g0+g1+g2)*(1.f/6.f);
        a[2][c] = (-g0+g1-g2)*(1.f/6.f);
        a[3][c] = g0*(1.f/24.f) + g1*(1.f/12.f) + g2*(1.f/6.f);
        a[4][c] = g0*(1.f/24.f) - g1*(1.f/12.f) + g2*(1.f/6.f);
        a[5][c] = g2;
    }
    #pragma unroll
    for (int i = 0; i < 6; i++) {
        float b0 = a[i][0], b1 = a[i][1], b2 = a[i][2];
        float u[6];
        u[0] = 0.25f*b0;
        u[1] = -(b0+b1+b2)*(1.f/6.f);
        u[2] = (-b0+b1-b2)*(1.f/6.f);
        u[3] = b0*(1.f/24.f) + b1*(1.f/12.f) + b2*(1.f/6.f);
        u[4] = b0*(1.f/24.f) - b1*(1.f/12.f) + b2*(1.f/6.f);
        u[5] = b2;
        #pragma unroll
        for (int j = 0; j < 6; j++) {
            size_t base = ((size_t)(i*6+j)*CIN + ci)*(2*C2) + 2*o;
            U[base]     = u[j];
            U[base + 1] = u[j];
        }
    }
}

// ---------------- bilinear 2x upsample * s1 (2 X-pixels per thread) ----------------
__global__ void k_upmod(const float* __restrict__ x)
{
    size_t t = (size_t)blockIdx.x*blockDim.x + threadIdx.x;
    if (t >= (size_t)BB*C1*NPIX/2) return;
    int ph = (int)(t % (NPIX/2));
    int bc = (int)(t / (NPIX/2));
    int Y = ph >> 6;
    int tX = ph & 63;
    float sy = Y*0.5f - 0.25f;
    int y0 = (int)floorf(sy); float fy = sy - (float)y0;
    int y0c = max(y0, 0), y1c = min(y0+1, H0-1);
    const float* xp = x + (size_t)bc*NPIX0;
    const float* r0 = xp + y0c*H0;
    const float* r1 = xp + y1c*H0;
    float s = g_s1[bc];
    int xm = max(tX-1, 0), xc = tX, xpn = min(tX+1, H0-1);
    float a0 = r0[xm], a1 = r0[xc], a2 = r0[xpn];
    float b0 = r1[xm], b1 = r1[xc], b2 = r1[xpn];
    float top0 = 0.25f*a0 + 0.75f*a1;
    float bot0 = 0.25f*b0 + 0.75f*b1;
    float top1 = 0.75f*a1 + 0.25f*a2;
    float bot1 = 0.75f*b1 + 0.25f*b2;
    float v0 = ((1.f-fy)*top0 + fy*bot0) * s;
    float v1 = ((1.f-fy)*top1 + fy*bot1) * s;
    *reinterpret_cast<float2*>(&g_up[(size_t)bc*NPIX + Y*H1 + tX*2]) = make_float2(v0, v1);
}

// ---------------- F(4,3) input transform: V[t][ci][tile] = (B^T d B)[t], pad=1 ----------------
__global__ void k_itrans4(const float* __restrict__ in, float* __restrict__ V, int CIN)
{
    int idx = blockIdx.x*256 + threadIdx.x;    // ci*NT4 + tile; tile = (b<<10)|(ty<<5)|txt
    if (idx >= CIN*NT4) return;
    int txt = idx & 31, ty = (idx >> 5) & 31, b = (idx >> 10) & 7, ci = idx >> 13;
    int tile = idx & (NT4-1);
    const float* src = in + ((size_t)(b*CIN + ci) << 14);
    int r0 = 4*ty - 1, c0 = 4*txt - 1;
    float t[6][6];
    #pragma unroll
    for (int c = 0; c < 6; c++) {
        int xx = c0 + c;
        bool ox = ((unsigned)xx < (unsigned)H1);
        float d0, d1, d2, d3, d4, d5;
        {
            int y;
            y = r0 + 0; d0 = (ox && (unsigned)y < (unsigned)H1) ? src[y*H1 + xx] : 0.f;
            y = r0 + 1; d1 = (ox && (unsigned)y < (unsigned)H1) ? src[y*H1 + xx] : 0.f;
            y = r0 + 2; d2 = (ox && (unsigned)y < (unsigned)H1) ? src[y*H1 + xx] : 0.f;
            y = r0 + 3; d3 = (ox && (unsigned)y < (unsigned)H1) ? src[y*H1 + xx] : 0.f;
            y = r0 + 4; d4 = (ox && (unsigned)y < (unsigned)H1) ? src[y*H1 + xx] : 0.f;
            y = r0 + 5; d5 = (ox && (unsigned)y < (unsigned)H1) ? src[y*H1 + xx] : 0.f;
        }
        t[0][c] = 4.f*d0 - 5.f*d2 + d4;
        t[1][c] = -4.f*d1 - 4.f*d2 + d3 + d4;
        t[2][c] = 4.f*d1 - 4.f*d2 - d3 + d4;
        t[3][c] = -2.f*d1 - d2 + 2.f*d3 + d4;
        t[4][c] = 2.f*d1 - d2 - 2.f*d3 + d4;
        t[5][c] = 4.f*d1 - 5.f*d3 + d5;
    }
    #pragma unroll
    for (int r = 0; r < 6; r++) {
        float t0 = t[r][0], t1 = t[r][1], t2 = t[r][2], t3 = t[r][3], t4 = t[r][4], t5 = t[r][5];
        float v0 = 4.f*t0 - 5.f*t2 + t4;
        float v1 = -4.f*t1 - 4.f*t2 + t3 + t4;
        float v2 = 4.f*t1 - 4.f*t2 - t3 + t4;
        float v3 = -2.f*t1 - t2 + 2.f*t3 + t4;
        float v4 = 2.f*t1 - t2 - 2.f*t3 + t4;
        float v5 = 4.f*t1 - 5.f*t3 + t5;
        V[((size_t)(r*6+0)*CIN + ci)*NT4 + tile] = v0;
        V[((size_t)(r*6+1)*CIN + ci)*NT4 + tile] = v1;
        V[((size_t)(r*6+2)*CIN + ci)*NT4 + tile] = v2;
        V[((size_t)(r*6+3)*CIN + ci)*NT4 + tile] = v3;
        V[((size_t)(r*6+4)*CIN + ci)*NT4 + tile] = v4;
        V[((size_t)(r*6+5)*CIN + ci)*NT4 + tile] = v5;
    }
}

// ---------------- winograd GEMM, tile-paired accumulators ----------------
// CTA: 32 o x 256 tiles, 128 threads. po=tid/32 -> 8 o's; tx=tid&31 -> tile pairs
// (2tx+64j, +1), j=0..3. vb = LDS.64 from sV (tiles adjacent); up = LDS.64 from
// pre-duplicated sU {u,u}. Grid: x = o-block (fastest -> L2 reuse of V), y = tiles, z = tap.
#define GKC 8
template<int CIN>
__global__ __launch_bounds__(128, 4)
void k_gemm(const float* __restrict__ U, const float* __restrict__ V, float* __restrict__ M)
{
    __shared__ __align__(16) float sV[2][GKC*256];   // 16 KB
    __shared__ __align__(16) float sU[2][GKC*64];    // 4 KB (duplicated pairs)

    int tid = threadIdx.x;
    int po  = tid >> 5;
    int tx  = tid & 31;
    int o0    = blockIdx.x * 32;
    int tile0 = blockIdx.y * 256;
    int tap   = blockIdx.z;

    const float* Vt = V + (size_t)tap*CIN*NT4;
    const float* Ut = U + (size_t)tap*CIN*(2*C2);
    uint32_t sV_a = smem_u32(&sV[0][0]);
    uint32_t sU_a = smem_u32(&sU[0][0]);

    auto fill = [&](int k, int buf) {
        int ci0 = k*GKC;
        for (int i = tid; i < GKC*64; i += 128) {
            int ci = i >> 6, v = i & 63;
            cp16(sV_a + (uint32_t)(buf*(GKC*256) + ci*256 + v*4)*4u,
                 Vt + (size_t)(ci0+ci)*NT4 + tile0 + v*4);
        }
        {   // U dup: 8 ci x 64 floats = 128 cp16, one per thread
            int ci = tid >> 4, v = tid & 15;
            cp16(sU_a + (uint32_t)(buf*(GKC*64) + ci*64 + v*4)*4u,
                 Ut + (size_t)(ci0+ci)*(2*C2) + 2*o0 + v*4);
        }
        CP_COMMIT();
    };

    ull acc2[8][4];
    #pragma unroll
    for (int oo = 0; oo < 8; oo++)
        #pragma unroll
        for (int j = 0; j < 4; j++) acc2[oo][j] = 0ULL;

    fill(0, 0);

    const int NCHUNK = CIN / GKC;
    for (int k = 0; k < NCHUNK; k++) {
        int buf = k & 1;
        asm volatile("cp.async.wait_group 0;" ::: "memory");
        __syncthreads();
        if (k + 1 < NCHUNK) fill(k + 1, buf ^ 1);

        const float* bV = &sV[buf][0];
        const float* bU = &sU[buf][0];
        #pragma unroll
        for (int ci = 0; ci < GKC; ci++) {
            ull vb[4];
            #pragma unroll
            for (int j = 0; j < 4; j++)
                vb[j] = *reinterpret_cast<const ull*>(&bV[ci*256 + 2*tx + 64*j]);
            ull up[8];
            #pragma unroll
            for (int oo = 0; oo < 8; oo++)
                up[oo] = *reinterpret_cast<const ull*>(&bU[ci*64 + po*16 + 2*oo]);
            #pragma unroll
            for (int oo = 0; oo < 8; oo++)
                #pragma unroll
                for (int j = 0; j < 4; j++)
                    ffma2(acc2[oo][j], up[oo], vb[j]);
        }
    }

    float* Mt = M + (size_t)tap*C2*NT4;
    #pragma unroll
    for (int oo = 0; oo < 8; oo++) {
        int o = o0 + po*8 + oo;
        #pragma unroll
        for (int j = 0; j < 4; j++)
            *reinterpret_cast<ull*>(&Mt[(size_t)o*NT4 + tile0 + 2*tx + 64*j]) = acc2[oo][j];
    }
}

// ---------------- F(4,3) inverse transform + epilogue ----------------
template<bool MULS2>
__global__ void k_inv4(const float* __restrict__ emod, const float* __restrict__ smod2,
                       const float* __restrict__ noise, const float* __restrict__ nw,
                       float* __restrict__ out)
{
    int idx = blockIdx.x*256 + threadIdx.x;    // o*NT4 + tile
    if (idx >= C2*NT4) return;
    int txt = idx & 31, ty = (idx >> 5) & 31, b = (idx >> 10) & 7, o = idx >> 13;
    int tile = idx & (NT4-1);

    float s[4][6];
    #pragma unroll
    for (int c = 0; c < 6; c++) {
        float m0 = g_M[((size_t)(0*6+c)*C2 + o)*NT4 + tile];
        float m1 = g_M[((size_t)(1*6+c)*C2 + o)*NT4 + tile];
        float m2 = g_M[((size_t)(2*6+c)*C2 + o)*NT4 + tile];
        float m3 = g_M[((size_t)(3*6+c)*C2 + o)*NT4 + tile];
        float m4 = g_M[((size_t)(4*6+c)*C2 + o)*NT4 + tile];
        float m5 = g_M[((size_t)(5*6+c)*C2 + o)*NT4 + tile];
        s[0][c] = m0 + m1 + m2 + m3 + m4;
        s[1][c] = m1 - m2 + 2.f*m3 - 2.f*m4;
        s[2][c] = m1 + m2 + 4.f*m3 + 4.f*m4;
        s[3][c] = m1 - m2 + 8.f*m3 - 8.f*m4 + m5;
    }

    int Y0 = 4*ty, X0 = 4*txt;
    float e = emod[b*C2 + o];
    float nwv = nw[0];
    float s2v = MULS2 ? smod2[b*C2 + o] : 1.f;
    const float* nz = noise + ((size_t)b << 14);
    float* dst = out + ((size_t)(b*C2 + o) << 14);

    #pragma unroll
    for (int r = 0; r < 4; r++) {
        float t0 = s[r][0], t1 = s[r][1], t2 = s[r][2], t3 = s[r][3], t4 = s[r][4], t5 = s[r][5];
        float y0 = t0 + t1 + t2 + t3 + t4;
        float y1 = t1 - t2 + 2.f*t3 - 2.f*t4;
        float y2 = t1 + t2 + 4.f*t3 + 4.f*t4;
        float y3 = t1 - t2 + 8.f*t3 - 8.f*t4 + t5;
        int row = (Y0 + r)*H1 + X0;
        float v0 = y0*e + nwv*nz[row];     v0 = (v0>0.f)?v0:0.2f*v0; v0 *= s2v;
        float v1 = y1*e + nwv*nz[row+1];   v1 = (v1>0.f)?v1:0.2f*v1; v1 *= s2v;
        float v2 = y2*e + nwv*nz[row+2];   v2 = (v2>0.f)?v2:0.2f*v2; v2 *= s2v;
        float v3 = y3*e + nwv*nz[row+3];   v3 = (v3>0.f)?v3:0.2f*v3; v3 *= s2v;
        *reinterpret_cast<float4*>(&dst[row]) = make_float4(v0, v1, v2, v3);
    }
}

// ---------------- to_rgb 1x1 (no demod) + upsampled skip ----------------
__global__ void k_rgb(const float* __restrict__ h, const float* __restrict__ rgbw,
                      const float* __restrict__ skip, float* __restrict__ outrgb)
{
    int b = blockIdx.y;
    __shared__ float sw[3][C2];
    for (int i = threadIdx.x; i < 3*C2; i += blockDim.x) {
        int c = i / C2, o = i % C2;
        sw[c][o] = rgbw[c*C2 + o] * g_s3[b*C2 + o] * 0.0625f;  // 1/sqrt(256)
    }
    __syncthreads();
    int p = blockIdx.x*blockDim.x + threadIdx.x;
    float a0 = 0.f, a1 = 0.f, a2 = 0.f;
    for (int o = 0; o < C2; o++) {
        float v = h[(size_t)(b*C2 + o)*NPIX + p];
        a0 += sw[0][o]*v; a1 += sw[1][o]*v; a2 += sw[2][o]*v;
    }
    int X = p % H1, Y = p / H1;
    float sy = Y*0.5f - 0.25f, sx = X*0.5f - 0.25f;
    int y0 = (int)floorf(sy), x0 = (int)floorf(sx);
    float fy = sy - (float)y0, fx = sx - (float)x0;
    int y0c = max(y0, 0), y1c = min(y0+1, H0-1);
    int x0c = max(x0, 0), x1c = min(x0+1, H0-1);
    float a[3] = {a0, a1, a2};
    #pragma unroll
    for (int c = 0; c < 3; c++) {
        const float* sp = skip + (size_t)(b*3 + c)*NPIX0;
        float bv = (1.f-fy)*((1.f-fx)*sp[y0c*H0+x0c] + fx*sp[y0c*H0+x1c])
                 +      fy *((1.f-fx)*sp[y1c*H0+x0c] + fx*sp[y1c*H0+x1c]);
        outrgb[(size_t)(b*3 + c)*NPIX + p] = a[c] + bv;
    }
}

// ---------------- launch ----------------
extern "C" void kernel_launch(void* const* d_in, const int* in_sizes, int n_in,
                              void* d_out, int out_size)
{
    const float* x       = (const float*)d_in[0];
    const float* w1      = (const float*)d_in[1];
    const float* w2      = (const float*)d_in[2];
    const float* skip    = (const float*)d_in[3];
    const float* noise1  = (const float*)d_in[4];
    const float* noise2  = (const float*)d_in[5];
    const float* conv1_w = (const float*)d_in[6];
    const float* mod1_w  = (const float*)d_in[7];
    const float* mod1_b  = (const float*)d_in[8];
    const float* conv2_w = (const float*)d_in[9];
    const float* mod2_w  = (const float*)d_in[10];
    const float* mod2_b  = (const float*)d_in[11];
    const float* rgb_w   = (const float*)d_in[12];
    const float* mod3_w  = (const float*)d_in[13];
    const float* mod3_b  = (const float*)d_in[14];
    const float* nw1     = (const float*)d_in[15];
    const float* nw2     = (const float*)d_in[16];
    float* out = (float*)d_out;

    void *p_up, *p_h1, *p_e1, *p_e2, *p_s2, *p_U1, *p_U2, *p_V, *p_M;
    cudaGetSymbolAddress(&p_up, g_up);
    cudaGetSymbolAddress(&p_h1, g_h1);
    cudaGetSymbolAddress(&p_e1, g_e1);
    cudaGetSymbolAddress(&p_e2, g_e2);
    cudaGetSymbolAddress(&p_s2, g_s2);
    cudaGetSymbolAddress(&p_U1, g_U1);
    cudaGetSymbolAddress(&p_U2, g_U2);
    cudaGetSymbolAddress(&p_V,  g_V);
    cudaGetSymbolAddress(&p_M,  g_M);

    float* out_h   = out;                                // [8,256,128,128]
    float* out_rgb = out + (size_t)BB*C2*NPIX;           // [8,3,128,128]

    // 1. styles + demod scalars
    {
        int n = BB*C1 + 2*BB*C2;
        k_styles<<<(n + 255)/256, 256>>>(w1, w2, mod1_w, mod1_b, mod2_w, mod2_b, mod3_w, mod3_b);
    }
    {
        int n = C2*C1 + C2*C2;
        k_wsq<<<(n + 255)/256, 256>>>(conv1_w, conv2_w);
    }
    k_demod<<<(2*BB*C2 + 255)/256, 256>>>();
    // 2. F(4,3) weight transforms (duplicated pairs)
    k_wt4<<<(C1*C2 + 255)/256, 256>>>(conv1_w, (float*)p_U1, C1);
    k_wt4<<<(C2*C2 + 255)/256, 256>>>(conv2_w, (float*)p_U2, C2);
    // 3. upsample + modulate(s1)
    {
        size_t n = (size_t)BB*C1*NPIX/2;
        k_upmod<<<(unsigned)((n + 255)/256), 256>>>(x);
    }
    // 4. conv1 via winograd F(4x4,3x3)
    k_itrans4<<<(C1*NT4)/256, 256>>>((const float*)p_up, (float*)p_V, C1);
    k_gemm<C1><<<dim3(C2/32, NT4/256, 36), 128>>>((const float*)p_U1, (const float*)p_V, (float*)p_M);
    k_inv4<true><<<(C2*NT4)/256, 256>>>((const float*)p_e1, (const float*)p_s2, noise1, nw1, (float*)p_h1);
    // 5. conv2 via winograd F(4x4,3x3) (reuse V, M)
    k_itrans4<<<(C2*NT4)/256, 256>>>((const float*)p_h1, (float*)p_V, C2);
    k_gemm<C2><<<dim3(C2/32, NT4/256, 36), 128>>>((const float*)p_U2, (const float*)p_V, (float*)p_M);
    k_inv4<false><<<(C2*NT4)/256, 256>>>((const float*)p_e2, nullptr, noise2, nw2, out_h);
    // 6. to_rgb + upsampled skip
    k_rgb<<<dim3(NPIX/256, BB), 256>>>(out_h, rgb_w, skip, out_rgb);
}

// round 17
// speedup vs baseline: 1.1410x; 1.1410x over previous
#include <cuda_runtime.h>
#include <math.h>
#include <stdint.h>

#define BB   8
#define C1   512
#define C2   256
#define SD   512
#define H0   64
#define H1   128
#define NPIX   (H1*H1)      // 16384
#define NPIX0  (H0*H0)      // 4096
#define NT4  8192           // 4x4 output tiles: 8 b * 32 * 32

typedef unsigned long long ull;

__device__ __forceinline__ void ffma2(ull& acc, ull a, ull b) {
    asm("fma.rn.f32x2 %0, %1, %2, %0;" : "+l"(acc) : "l"(a), "l"(b));
}
__device__ __forceinline__ ull bcast2(float v) {
    ull p;
    asm("mov.b64 %0, {%1, %1};" : "=l"(p) : "r"(__float_as_uint(v)));
    return p;
}
__device__ __forceinline__ void unpack2(ull p, float& lo, float& hi) {
    unsigned int a, b;
    asm("mov.b64 {%0, %1}, %2;" : "=r"(a), "=r"(b) : "l"(p));
    lo = __uint_as_float(a); hi = __uint_as_float(b);
}
__device__ __forceinline__ uint32_t smem_u32(const void* p) {
    uint32_t a;
    asm("{ .reg .u64 t; cvta.to.shared.u64 t, %1; cvt.u32.u64 %0, t; }" : "=r"(a) : "l"(p));
    return a;
}
__device__ __forceinline__ void cp16(uint32_t dst, const float* src) {
    asm volatile("cp.async.ca.shared.global [%0], [%1], 16;" :: "r"(dst), "l"(src));
}
#define CP_COMMIT() asm volatile("cp.async.commit_group;")

// ---------------- scratch (device globals; no allocation) ----------------
__device__ float g_s1[BB*C1];
__device__ float g_s2[BB*C2];
__device__ float g_s3[BB*C2];
__device__ float g_e1[BB*C2];
__device__ float g_e2[BB*C2];
__device__ float g_wsq1[C2*C1];
__device__ float g_wsq2[C2*C2];
__device__ float g_h1 [(size_t)BB*C2*NPIX];        // 134 MB conv1 out * s2
__device__ float g_U1 [(size_t)36*C1*C2];          // 18.9 MB winograd weights [t][ci][o]
__device__ float g_U2 [(size_t)36*C2*C2];          // 9.4 MB
__device__ float g_V  [(size_t)36*C1*NT4];         // 604 MB transformed input [t][ci][tile]
__device__ float g_M  [(size_t)36*C2*NT4];         // 302 MB GEMM out [t][o][tile]

// ---------------- styles ----------------
__global__ void k_styles(const float* __restrict__ w1, const float* __restrict__ w2,
                         const float* __restrict__ m1w, const float* __restrict__ m1b,
                         const float* __restrict__ m2w, const float* __restrict__ m2b,
                         const float* __restrict__ m3w, const float* __restrict__ m3b)
{
    int t = blockIdx.x*blockDim.x + threadIdx.x;
    const float inv = rsqrtf((float)SD);
    if (t < BB*C1) {
        int b = t / C1, i = t % C1;
        float a = 0.f;
        for (int k = 0; k < SD; k++) a += w1[b*SD+k] * m1w[i*SD+k];
        g_s1[t] = a*inv + m1b[i];
    } else if (t < BB*C1 + BB*C2) {
        int u = t - BB*C1; int b = u / C2, i = u % C2;
        float a = 0.f;
        for (int k = 0; k < SD; k++) a += w2[b*SD+k] * m2w[i*SD+k];
        g_s2[u] = a*inv + m2b[i];
    } else if (t < BB*C1 + 2*BB*C2) {
        int u = t - BB*C1 - BB*C2; int b = u / C2, i = u % C2;
        float a = 0.f;
        for (int k = 0; k < SD; k++) a += w2[b*SD+k] * m3w[i*SD+k];
        g_s3[u] = a*inv + m3b[i];
    }
}

// ---------------- per-(o,i) sum of squared taps ----------------
__global__ void k_wsq(const float* __restrict__ w1c, const float* __restrict__ w2c)
{
    int t = blockIdx.x*blockDim.x + threadIdx.x;
    if (t < C2*C1) {
        float a = 0.f;
        #pragma unroll
        for (int k = 0; k < 9; k++) { float v = w1c[t*9+k]; a += v*v; }
        g_wsq1[t] = a;
    } else if (t < C2*C1 + C2*C2) {
        int u = t - C2*C1;
        float a = 0.f;
        #pragma unroll
        for (int k = 0; k < 9; k++) { float v = w2c[u*9+k]; a += v*v; }
        g_wsq2[u] = a;
    }
}

// ---------------- demod scalars ----------------
__global__ void k_demod()
{
    int t = blockIdx.x*blockDim.x + threadIdx.x;
    const float sc1 = rsqrtf((float)(C1*9));
    const float sc2 = rsqrtf((float)(C2*9));
    if (t < BB*C2) {
        int b = t / C2, o = t % C2;
        float a = 0.f;
        for (int i = 0; i < C1; i++) { float s = g_s1[b*C1+i]; a += g_wsq1[o*C1+i]*s*s; }
        g_e1[t] = sc1 * rsqrtf(sc1*sc1*a + 1e-8f);
    } else if (t < 2*BB*C2) {
        int u = t - BB*C2; int b = u / C2, o = u % C2;
        float a = 0.f;
        for (int i = 0; i < C2; i++) { float s = g_s2[b*C2+i]; a += g_wsq2[o*C2+i]*s*s; }
        g_e2[u] = sc2 * rsqrtf(sc2*sc2*a + 1e-8f);
    }
}

// ---------------- F(4,3) weight transform: U[t][ci][o] = (G g G^T)[t] ----------------
__global__ void k_wt4(const float* __restrict__ w, float* __restrict__ U, int CIN)
{
    int idx = blockIdx.x*256 + threadIdx.x;
    if (idx >= CIN*C2) return;
    int o = idx & 255, ci = idx >> 8;
    const float* g = w + ((size_t)o*CIN + ci)*9;   // g[ky*3+kx]
    float a[6][3];
    #pragma unroll
    for (int c = 0; c < 3; c++) {
        float g0 = g[c], g1 = g[3+c], g2 = g[6+c];
        a[0][c] = 0.25f*g0;
        a[1][c] = -(g0+g1+g2)*(1.f/6.f);
        a[2][c] = (-g0+g1-g2)*(1.f/6.f);
        a[3][c] = g0*(1.f/24.f) + g1*(1.f/12.f) + g2*(1.f/6.f);
        a[4][c] = g0*(1.f/24.f) - g1*(1.f/12.f) + g2*(1.f/6.f);
        a[5][c] = g2;
    }
    #pragma unroll
    for (int i = 0; i < 6; i++) {
        float b0 = a[i][0], b1 = a[i][1], b2 = a[i][2];
        float u[6];
        u[0] = 0.25f*b0;
        u[1] = -(b0+b1+b2)*(1.f/6.f);
        u[2] = (-b0+b1-b2)*(1.f/6.f);
        u[3] = b0*(1.f/24.f) + b1*(1.f/12.f) + b2*(1.f/6.f);
        u[4] = b0*(1.f/24.f) - b1*(1.f/12.f) + b2*(1.f/6.f);
        u[5] = b2;
        #pragma unroll
        for (int j = 0; j < 6; j++)
            U[((size_t)(i*6+j)*CIN + ci)*C2 + o] = u[j];
    }
}

// ---------------- FUSED: upsample2x*s1 + F(4,3) input transform (conv1) ----------------
// Fine pixel 4t-1+i maps to staged coarse row (i>>1) with fy = 0.25 + 0.5*(i&1).
// Coarse block needed: rows 2ty-1..2ty+2, cols 2txt-1..2txt+2 (clamped) = 4x4.
__global__ void k_itrans4up(const float* __restrict__ x, float* __restrict__ V)
{
    int idx = blockIdx.x*256 + threadIdx.x;    // ci*NT4 + tile; tile = (b<<10)|(ty<<5)|txt
    if (idx >= C1*NT4) return;
    int txt = idx & 31, ty = (idx >> 5) & 31, b = (idx >> 10) & 7, ci = idx >> 13;
    int tile = idx & (NT4-1);
    const float* src = x + ((size_t)(b*C1 + ci) << 12);   // 64x64
    float s = g_s1[b*C1 + ci];

    // stage clamped 4x4 coarse block
    float cc[4][4];
    int cy0 = 2*ty - 1, cx0 = 2*txt - 1;
    #pragma unroll
    for (int r = 0; r < 4; r++) {
        int cy = min(max(cy0 + r, 0), H0-1);
        const float* rowp = src + cy*H0;
        #pragma unroll
        for (int c = 0; c < 4; c++) {
            int cx = min(max(cx0 + c, 0), H0-1);
            cc[r][c] = rowp[cx];
        }
    }

    // fine 6x6 d = bilinear * s1, zero at fine OOB (conv padding)
    float d[6][6];
    #pragma unroll
    for (int i = 0; i < 6; i++) {
        bool oy = ((unsigned)(4*ty - 1 + i) < (unsigned)H1);
        int rl = i >> 1;
        float fy = (i & 1) ? 0.75f : 0.25f;
        float gy0w = 1.f - fy;
        #pragma unroll
        for (int j = 0; j < 6; j++) {
            bool ox = ((unsigned)(4*txt - 1 + j) < (unsigned)H1);
            if (oy && ox) {
                int cl = j >> 1;
                float fx = (j & 1) ? 0.75f : 0.25f;
                float v = gy0w*((1.f-fx)*cc[rl][cl]   + fx*cc[rl][cl+1])
                        +   fy*((1.f-fx)*cc[rl+1][cl] + fx*cc[rl+1][cl+1]);
                d[i][j] = v * s;
            } else {
                d[i][j] = 0.f;
            }
        }
    }

    // B^T d B
    float t[6][6];
    #pragma unroll
    for (int c = 0; c < 6; c++) {
        float d0 = d[0][c], d1 = d[1][c], d2 = d[2][c], d3 = d[3][c], d4 = d[4][c], d5 = d[5][c];
        t[0][c] = 4.f*d0 - 5.f*d2 + d4;
        t[1][c] = -4.f*d1 - 4.f*d2 + d3 + d4;
        t[2][c] = 4.f*d1 - 4.f*d2 - d3 + d4;
        t[3][c] = -2.f*d1 - d2 + 2.f*d3 + d4;
        t[4][c] = 2.f*d1 - d2 - 2.f*d3 + d4;
        t[5][c] = 4.f*d1 - 5.f*d3 + d5;
    }
    #pragma unroll
    for (int r = 0; r < 6; r++) {
        float t0 = t[r][0], t1 = t[r][1], t2 = t[r][2], t3 = t[r][3], t4 = t[r][4], t5 = t[r][5];
        V[((size_t)(r*6+0)*C1 + ci)*NT4 + tile] = 4.f*t0 - 5.f*t2 + t4;
        V[((size_t)(r*6+1)*C1 + ci)*NT4 + tile] = -4.f*t1 - 4.f*t2 + t3 + t4;
        V[((size_t)(r*6+2)*C1 + ci)*NT4 + tile] = 4.f*t1 - 4.f*t2 - t3 + t4;
        V[((size_t)(r*6+3)*C1 + ci)*NT4 + tile] = -2.f*t1 - t2 + 2.f*t3 + t4;
        V[((size_t)(r*6+4)*C1 + ci)*NT4 + tile] = 2.f*t1 - t2 - 2.f*t3 + t4;
        V[((size_t)(r*6+5)*C1 + ci)*NT4 + tile] = 4.f*t1 - 5.f*t3 + t5;
    }
}

// ---------------- F(4,3) input transform (plain, conv2): V = B^T d B, pad=1 ----------------
__global__ void k_itrans4(const float* __restrict__ in, float* __restrict__ V, int CIN)
{
    int idx = blockIdx.x*256 + threadIdx.x;
    if (idx >= CIN*NT4) return;
    int txt = idx & 31, ty = (idx >> 5) & 31, b = (idx >> 10) & 7, ci = idx >> 13;
    int tile = idx & (NT4-1);
    const float* src = in + ((size_t)(b*CIN + ci) << 14);
    int r0 = 4*ty - 1, c0 = 4*txt - 1;
    float t[6][6];
    #pragma unroll
    for (int c = 0; c < 6; c++) {
        int xx = c0 + c;
        bool ox = ((unsigned)xx < (unsigned)H1);
        float d0, d1, d2, d3, d4, d5;
        {
            int y;
            y = r0 + 0; d0 = (ox && (unsigned)y < (unsigned)H1) ? src[y*H1 + xx] : 0.f;
            y = r0 + 1; d1 = (ox && (unsigned)y < (unsigned)H1) ? src[y*H1 + xx] : 0.f;
            y = r0 + 2; d2 = (ox && (unsigned)y < (unsigned)H1) ? src[y*H1 + xx] : 0.f;
            y = r0 + 3; d3 = (ox && (unsigned)y < (unsigned)H1) ? src[y*H1 + xx] : 0.f;
            y = r0 + 4; d4 = (ox && (unsigned)y < (unsigned)H1) ? src[y*H1 + xx] : 0.f;
            y = r0 + 5; d5 = (ox && (unsigned)y < (unsigned)H1) ? src[y*H1 + xx] : 0.f;
        }
        t[0][c] = 4.f*d0 - 5.f*d2 + d4;
        t[1][c] = -4.f*d1 - 4.f*d2 + d3 + d4;
        t[2][c] = 4.f*d1 - 4.f*d2 - d3 + d4;
        t[3][c] = -2.f*d1 - d2 + 2.f*d3 + d4;
        t[4][c] = 2.f*d1 - d2 - 2.f*d3 + d4;
        t[5][c] = 4.f*d1 - 5.f*d3 + d5;
    }
    #pragma unroll
    for (int r = 0; r < 6; r++) {
        float t0 = t[r][0], t1 = t[r][1], t2 = t[r][2], t3 = t[r][3], t4 = t[r][4], t5 = t[r][5];
        V[((size_t)(r*6+0)*CIN + ci)*NT4 + tile] = 4.f*t0 - 5.f*t2 + t4;
        V[((size_t)(r*6+1)*CIN + ci)*NT4 + tile] = -4.f*t1 - 4.f*t2 + t3 + t4;
        V[((size_t)(r*6+2)*CIN + ci)*NT4 + tile] = 4.f*t1 - 4.f*t2 - t3 + t4;
        V[((size_t)(r*6+3)*CIN + ci)*NT4 + tile] = -2.f*t1 - t2 + 2.f*t3 + t4;
        V[((size_t)(r*6+4)*CIN + ci)*NT4 + tile] = 2.f*t1 - t2 - 2.f*t3 + t4;
        V[((size_t)(r*6+5)*CIN + ci)*NT4 + tile] = 4.f*t1 - 5.f*t3 + t5;
    }
}

// ---------------- winograd GEMM (R15 structure, o-paired accumulators) ----------------
// CTA: 32 o x 256 tiles, 128 threads (po=tid/32: 8 o as 4 pairs; tx: 8 tiles stride 32).
#define GKC 8
template<int CIN>
__global__ __launch_bounds__(128, 4)
void k_gemm(const float* __restrict__ U, const float* __restrict__ V, float* __restrict__ M)
{
    __shared__ __align__(16) float sV[2][GKC*256];   // 16 KB
    __shared__ __align__(16) float sU[2][GKC*32];    // 2 KB

    int tid = threadIdx.x;
    int po  = tid >> 5;
    int tx  = tid & 31;
    int tile0 = blockIdx.x * 256;
    int o0    = blockIdx.y * 32;
    int tap   = blockIdx.z;

    const float* Vt = V + (size_t)tap*CIN*NT4;
    const float* Ut = U + (size_t)tap*CIN*C2;
    uint32_t sV_a = smem_u32(&sV[0][0]);
    uint32_t sU_a = smem_u32(&sU[0][0]);

    auto fill = [&](int k, int buf) {
        int ci0 = k*GKC;
        for (int i = tid; i < GKC*64; i += 128) {
            int ci = i >> 6, v = i & 63;
            cp16(sV_a + (uint32_t)(buf*(GKC*256) + ci*256 + v*4)*4u,
                 Vt + (size_t)(ci0+ci)*NT4 + tile0 + v*4);
        }
        if (tid < 64) {
            int ci = tid >> 3, v = tid & 7;
            cp16(sU_a + (uint32_t)(buf*(GKC*32) + ci*32 + v*4)*4u,
                 Ut + (size_t)(ci0+ci)*C2 + o0 + v*4);
        }
        CP_COMMIT();
    };

    ull acc2[4][8];
    #pragma unroll
    for (int q = 0; q < 4; q++)
        #pragma unroll
        for (int j = 0; j < 8; j++) acc2[q][j] = 0ULL;

    fill(0, 0);

    const int NCHUNK = CIN / GKC;
    for (int k = 0; k < NCHUNK; k++) {
        int buf = k & 1;
        asm volatile("cp.async.wait_group 0;" ::: "memory");
        __syncthreads();
        if (k + 1 < NCHUNK) fill(k + 1, buf ^ 1);

        const float* bV = &sV[buf][0];
        const float* bU = &sU[buf][0];
        #pragma unroll
        for (int ci = 0; ci < GKC; ci++) {
            ull vb[8];
            #pragma unroll
            for (int j = 0; j < 8; j++) vb[j] = bcast2(bV[ci*256 + tx + 32*j]);
            ull wp[4];
            #pragma unroll
            for (int q = 0; q < 4; q++)
                wp[q] = *reinterpret_cast<const ull*>(&bU[ci*32 + po*8 + q*2]);
            #pragma unroll
            for (int q = 0; q < 4; q++)
                #pragma unroll
                for (int j = 0; j < 8; j++)
                    ffma2(acc2[q][j], wp[q], vb[j]);
        }
    }

    float* Mt = M + (size_t)tap*C2*NT4;
    #pragma unroll
    for (int q = 0; q < 4; q++) {
        int o = o0 + po*8 + q*2;
        #pragma unroll
        for (int j = 0; j < 8; j++) {
            float a0, a1; unpack2(acc2[q][j], a0, a1);
            Mt[(size_t)o*NT4     + tile0 + tx + 32*j] = a0;
            Mt[(size_t)(o+1)*NT4 + tile0 + tx + 32*j] = a1;
        }
    }
}

// ---------------- F(4,3) inverse transform + epilogue ----------------
template<bool MULS2>
__global__ void k_inv4(const float* __restrict__ emod, const float* __restrict__ smod2,
                       const float* __restrict__ noise, const float* __restrict__ nw,
                       float* __restrict__ out)
{
    int idx = blockIdx.x*256 + threadIdx.x;    // o*NT4 + tile
    if (idx >= C2*NT4) return;
    int txt = idx & 31, ty = (idx >> 5) & 31, b = (idx >> 10) & 7, o = idx >> 13;
    int tile = idx & (NT4-1);

    float s[4][6];
    #pragma unroll
    for (int c = 0; c < 6; c++) {
        float m0 = g_M[((size_t)(0*6+c)*C2 + o)*NT4 + tile];
        float m1 = g_M[((size_t)(1*6+c)*C2 + o)*NT4 + tile];
        float m2 = g_M[((size_t)(2*6+c)*C2 + o)*NT4 + tile];
        float m3 = g_M[((size_t)(3*6+c)*C2 + o)*NT4 + tile];
        float m4 = g_M[((size_t)(4*6+c)*C2 + o)*NT4 + tile];
        float m5 = g_M[((size_t)(5*6+c)*C2 + o)*NT4 + tile];
        s[0][c] = m0 + m1 + m2 + m3 + m4;
        s[1][c] = m1 - m2 + 2.f*m3 - 2.f*m4;
        s[2][c] = m1 + m2 + 4.f*m3 + 4.f*m4;
        s[3][c] = m1 - m2 + 8.f*m3 - 8.f*m4 + m5;
    }

    int Y0 = 4*ty, X0 = 4*txt;
    float e = emod[b*C2 + o];
    float nwv = nw[0];
    float s2v = MULS2 ? smod2[b*C2 + o] : 1.f;
    const float* nz = noise + ((size_t)b << 14);
    float* dst = out + ((size_t)(b*C2 + o) << 14);

    #pragma unroll
    for (int r = 0; r < 4; r++) {
        float t0 = s[r][0], t1 = s[r][1], t2 = s[r][2], t3 = s[r][3], t4 = s[r][4], t5 = s[r][5];
        float y0 = t0 + t1 + t2 + t3 + t4;
        float y1 = t1 - t2 + 2.f*t3 - 2.f*t4;
        float y2 = t1 + t2 + 4.f*t3 + 4.f*t4;
        float y3 = t1 - t2 + 8.f*t3 - 8.f*t4 + t5;
        int row = (Y0 + r)*H1 + X0;
        float v0 = y0*e + nwv*nz[row];     v0 = (v0>0.f)?v0:0.2f*v0; v0 *= s2v;
        float v1 = y1*e + nwv*nz[row+1];   v1 = (v1>0.f)?v1:0.2f*v1; v1 *= s2v;
        float v2 = y2*e + nwv*nz[row+2];   v2 = (v2>0.f)?v2:0.2f*v2; v2 *= s2v;
        float v3 = y3*e + nwv*nz[row+3];   v3 = (v3>0.f)?v3:0.2f*v3; v3 *= s2v;
        *reinterpret_cast<float4*>(&dst[row]) = make_float4(v0, v1, v2, v3);
    }
}

// ---------------- to_rgb 1x1 (no demod) + upsampled skip ----------------
__global__ void k_rgb(const float* __restrict__ h, const float* __restrict__ rgbw,
                      const float* __restrict__ skip, float* __restrict__ outrgb)
{
    int b = blockIdx.y;
    __shared__ float sw[3][C2];
    for (int i = threadIdx.x; i < 3*C2; i += blockDim.x) {
        int c = i / C2, o = i % C2;
        sw[c][o] = rgbw[c*C2 + o] * g_s3[b*C2 + o] * 0.0625f;  // 1/sqrt(256)
    }
    __syncthreads();
    int p = blockIdx.x*blockDim.x + threadIdx.x;
    float a0 = 0.f, a1 = 0.f, a2 = 0.f;
    for (int o = 0; o < C2; o++) {
        float v = h[(size_t)(b*C2 + o)*NPIX + p];
        a0 += sw[0][o]*v; a1 += sw[1][o]*v; a2 += sw[2][o]*v;
    }
    int X = p % H1, Y = p / H1;
    float sy = Y*0.5f - 0.25f, sx = X*0.5f - 0.25f;
    int y0 = (int)floorf(sy), x0 = (int)floorf(sx);
    float fy = sy - (float)y0, fx = sx - (float)x0;
    int y0c = max(y0, 0), y1c = min(y0+1, H0-1);
    int x0c = max(x0, 0), x1c = min(x0+1, H0-1);
    float a[3] = {a0, a1, a2};
    #pragma unroll
    for (int c = 0; c < 3; c++) {
        const float* sp = skip + (size_t)(b*3 + c)*NPIX0;
        float bv = (1.f-fy)*((1.f-fx)*sp[y0c*H0+x0c] + fx*sp[y0c*H0+x1c])
                 +      fy *((1.f-fx)*sp[y1c*H0+x0c] + fx*sp[y1c*H0+x1c]);
        outrgb[(size_t)(b*3 + c)*NPIX + p] = a[c] + bv;
    }
}

// ---------------- launch ----------------
extern "C" void kernel_launch(void* const* d_in, const int* in_sizes, int n_in,
                              void* d_out, int out_size)
{
    const float* x       = (const float*)d_in[0];
    const float* w1      = (const float*)d_in[1];
    const float* w2      = (const float*)d_in[2];
    const float* skip    = (const float*)d_in[3];
    const float* noise1  = (const float*)d_in[4];
    const float* noise2  = (const float*)d_in[5];
    const float* conv1_w = (const float*)d_in[6];
    const float* mod1_w  = (const float*)d_in[7];
    const float* mod1_b  = (const float*)d_in[8];
    const float* conv2_w = (const float*)d_in[9];
    const float* mod2_w  = (const float*)d_in[10];
    const float* mod2_b  = (const float*)d_in[11];
    const float* rgb_w   = (const float*)d_in[12];
    const float* mod3_w  = (const float*)d_in[13];
    const float* mod3_b  = (const float*)d_in[14];
    const float* nw1     = (const float*)d_in[15];
    const float* nw2     = (const float*)d_in[16];
    float* out = (float*)d_out;

    void *p_h1, *p_e1, *p_e2, *p_s2, *p_U1, *p_U2, *p_V, *p_M;
    cudaGetSymbolAddress(&p_h1, g_h1);
    cudaGetSymbolAddress(&p_e1, g_e1);
    cudaGetSymbolAddress(&p_e2, g_e2);
    cudaGetSymbolAddress(&p_s2, g_s2);
    cudaGetSymbolAddress(&p_U1, g_U1);
    cudaGetSymbolAddress(&p_U2, g_U2);
    cudaGetSymbolAddress(&p_V,  g_V);
    cudaGetSymbolAddress(&p_M,  g_M);

    float* out_h   = out;                                // [8,256,128,128]
    float* out_rgb = out + (size_t)BB*C2*NPIX;           // [8,3,128,128]

    // 1. styles + demod scalars
    {
        int n = BB*C1 + 2*BB*C2;
        k_styles<<<(n + 255)/256, 256>>>(w1, w2, mod1_w, mod1_b, mod2_w, mod2_b, mod3_w, mod3_b);
    }
    {
        int n = C2*C1 + C2*C2;
        k_wsq<<<(n + 255)/256, 256>>>(conv1_w, conv2_w);
    }
    k_demod<<<(2*BB*C2 + 255)/256, 256>>>();
    // 2. F(4,3) weight transforms
    k_wt4<<<(C1*C2 + 255)/256, 256>>>(conv1_w, (float*)p_U1, C1);
    k_wt4<<<(C2*C2 + 255)/256, 256>>>(conv2_w, (float*)p_U2, C2);
    // 3. conv1 via winograd, upsample+modulate fused into the input transform
    k_itrans4up<<<(C1*NT4)/256, 256>>>(x, (float*)p_V);
    k_gemm<C1><<<dim3(NT4/256, C2/32, 36), 128>>>((const float*)p_U1, (const float*)p_V, (float*)p_M);
    k_inv4<true><<<(C2*NT4)/256, 256>>>((const float*)p_e1, (const float*)p_s2, noise1, nw1, (float*)p_h1);
    // 4. conv2 via winograd (reuse V, M)
    k_itrans4<<<(C2*NT4)/256, 256>>>((const float*)p_h1, (float*)p_V, C2);
    k_gemm<C2><<<dim3(NT4/256, C2/32, 36), 128>>>((const float*)p_U2, (const float*)p_V, (float*)p_M);
    k_inv4<false><<<(C2*NT4)/256, 256>>>((const float*)p_e2, nullptr, noise2, nw2, out_h);
    // 5. to_rgb + upsampled skip
    k_rgb<<<dim3(NPIX/256, BB), 256>>>(out_h, rgb_w, skip, out_rgb);
}